// round 9
// baseline (speedup 1.0000x reference)
#include <cuda_runtime.h>
#include <cstdint>

// DiffUnpool: out[b] = S[b] @ x[b]
//   S: [16, 2048, 256] f32   x: [16, 256, 256] f32   out: [16, 2048, 256] f32
// tf32 m16n8k8, PRE-CONVERTED (cvt.rna at staging, R5-proven arithmetic).
// CTA 128x64, 4 warps of 64x32. Register-staged double-buffered smem,
// one __syncthreads per K-chunk. Compute body: 4 LDSM + 8 LDS + 16 MMA per kk.

#define A_BUF 16384                  // 128 rows x 128B (32 tf32)
#define B_ROWB 288                   // 64 tf32 (256B) + 32B pad
#define B_BUF (32 * B_ROWB)          // 9216
#define OFF_B (2 * A_BUF)            // 32768
#define SM_BYTES (2 * A_BUF + 2 * B_BUF)   // 51200

static __device__ __forceinline__ uint32_t cvta_smem(const void* p) {
    uint32_t a;
    asm("{ .reg .u64 t; cvta.to.shared.u64 t, %1; cvt.u32.u64 %0, t; }"
        : "=r"(a) : "l"(p));
    return a;
}
static __device__ __forceinline__ uint32_t tf32c(float f) {
    uint32_t u;
    asm("cvt.rna.tf32.f32 %0, %1;" : "=r"(u) : "f"(f));
    return u;
}
static __device__ __forceinline__ uint4 cvt4(float4 v) {
    return make_uint4(tf32c(v.x), tf32c(v.y), tf32c(v.z), tf32c(v.w));
}

#define LDSM4(r0, r1, r2, r3, a) \
    asm volatile("ldmatrix.sync.aligned.m8n8.x4.shared.b16 {%0,%1,%2,%3}, [%4];" \
                 : "=r"(r0), "=r"(r1), "=r"(r2), "=r"(r3) : "r"(a))
#define LDSS(r, a) \
    asm volatile("ld.shared.b32 %0, [%1];" : "=r"(r) : "r"(a))

#define MMA(d, a, b0, b1) \
    asm volatile("mma.sync.aligned.m16n8k8.row.col.f32.tf32.tf32.f32 " \
                 "{%0,%1,%2,%3},{%4,%5,%6,%7},{%8,%9},{%0,%1,%2,%3};" \
                 : "+f"((d)[0]), "+f"((d)[1]), "+f"((d)[2]), "+f"((d)[3]) \
                 : "r"((a)[0]), "r"((a)[1]), "r"((a)[2]), "r"((a)[3]), "r"(b0), "r"(b1))

extern __shared__ char smbuf[];

__global__ __launch_bounds__(128, 2)
void diffunpool_tf32_v5(const float* __restrict__ S, const float* __restrict__ X,
                        float* __restrict__ O) {
    const int nt = blockIdx.x;   // 0..3  (N tiles of 64)
    const int mt = blockIdx.y;   // 0..15
    const int b  = blockIdx.z;   // 0..15

    const float* Sb = S + ((size_t)b * 2048 + (size_t)mt * 128) * 256;
    const float* Xb = X + (size_t)b * 65536 + (size_t)nt * 64;
    float*       Ob = O + ((size_t)b * 2048 + (size_t)mt * 128) * 256 + (size_t)nt * 64;

    const int tid = threadIdx.x, wid = tid >> 5, lane = tid & 31;
    const int wm = (wid & 1) * 64;       // 2 warp rows of 64
    const int wn = (wid >> 1) * 32;      // 2 warp cols of 32
    const uint32_t sb = cvta_smem(smbuf);

    // ---- A staging: thread owns seg (tid&7) of rows m = 16q + (tid>>3), q<8
    const int a_m0 = tid >> 3, a_seg = tid & 7;
    const float*   pA   = Sb + (size_t)a_m0 * 256 + a_seg * 4;      // + q*4096 + c*32
    const uint32_t aSts = (uint32_t)a_m0 * 128
                        + (uint32_t)((a_seg ^ (a_m0 & 7)) << 4);     // + q*2048 + buf*A_BUF

    // ---- B staging: thread owns seg (tid&15) of rows k = 8q + (tid>>4), q<4
    const int b_k0 = tid >> 4, b_seg = tid & 15;
    const float*   pB   = Xb + (size_t)b_k0 * 256 + b_seg * 4;      // + q*2048 + c*32*256
    const uint32_t bSts = OFF_B + (uint32_t)b_k0 * B_ROWB + (uint32_t)(b_seg << 4);

    // ---- fragment addressing (A formula R6-proven)
    const int m_low = (lane & 7) + ((lane >> 3) & 1) * 8;
    const int halfk = lane >> 4;
    const int sw    = lane & 7;
    const uint32_t aFrag = sb + (uint32_t)(wm + m_low) * 128;        // + buf*A_BUF + mf*2048 + segsw
    const uint32_t bFrag = sb + OFF_B + (uint32_t)(lane & 3) * B_ROWB
                         + (uint32_t)(wn + (lane >> 2)) * 4;         // + buf*B_BUF + kk*8*B_ROWB + j*32

    float d[4][4][4];
#pragma unroll
    for (int mf = 0; mf < 4; mf++)
#pragma unroll
        for (int j = 0; j < 4; j++)
#pragma unroll
            for (int r = 0; r < 4; r++) d[mf][j][r] = 0.0f;

    // ---- prologue: LDG chunk 0
    float4 va[8], vb[4];
#pragma unroll
    for (int q = 0; q < 8; q++) va[q] = *(const float4*)(pA + q * 4096);
#pragma unroll
    for (int q = 0; q < 4; q++) vb[q] = *(const float4*)(pB + q * 2048);

    for (int c = 0; c < 8; c++) {
        const uint32_t aOff = (uint32_t)(c & 1) * A_BUF;
        const uint32_t bOff = (uint32_t)(c & 1) * B_BUF;

        // ---- convert + store chunk c (tf32 bits into smem)
#pragma unroll
        for (int q = 0; q < 8; q++)
            *(uint4*)(smbuf + aOff + aSts + q * 2048) = cvt4(va[q]);
#pragma unroll
        for (int q = 0; q < 4; q++)
            *(uint4*)(smbuf + bOff + bSts + q * (8 * B_ROWB)) = cvt4(vb[q]);
        __syncthreads();

        // ---- prefetch chunk c+1 globals (consumed at next STS)
        if (c < 7) {
            const float* nA = pA + (c + 1) * 32;
#pragma unroll
            for (int q = 0; q < 8; q++) va[q] = *(const float4*)(nA + q * 4096);
            const float* nB = pB + (size_t)(c + 1) * 32 * 256;
#pragma unroll
            for (int q = 0; q < 4; q++) vb[q] = *(const float4*)(nB + q * 2048);
        }

        // ---- compute chunk c: 4 kk steps of k8
#pragma unroll
        for (int kk = 0; kk < 4; kk++) {
            uint32_t a[4][4];
            const uint32_t segsw = (uint32_t)(((2 * kk + halfk) ^ sw) << 4);
#pragma unroll
            for (int mf = 0; mf < 4; mf++) {
                uint32_t addr = aFrag + aOff + (uint32_t)(mf * 2048) + segsw;
                LDSM4(a[mf][0], a[mf][1], a[mf][2], a[mf][3], addr);
            }
            uint32_t b0[4], b1[4];
            const uint32_t bk = bFrag + bOff + (uint32_t)(kk * 8 * B_ROWB);
#pragma unroll
            for (int j = 0; j < 4; j++) {
                LDSS(b0[j], bk + j * 32);
                LDSS(b1[j], bk + j * 32 + 4 * B_ROWB);
            }
#pragma unroll
            for (int mf = 0; mf < 4; mf++)
#pragma unroll
                for (int j = 0; j < 4; j++)
                    MMA(d[mf][j], a[mf], b0[j], b1[j]);
        }
        // single barrier per chunk: next STS targets the other buffer; the
        // barrier above orders the last readers of that buffer (compute c-1)
        // before STS(c+1) in every warp's program order.
    }

    // ---- epilogue
    const int group = lane >> 2;
    const int tcol  = (lane & 3) * 2;
#pragma unroll
    for (int mf = 0; mf < 4; mf++) {
        int m0 = wm + mf * 16 + group;
#pragma unroll
        for (int j = 0; j < 4; j++) {
            int n0 = wn + j * 8 + tcol;
            *(float2*)(Ob + (size_t)m0 * 256 + n0)       = make_float2(d[mf][j][0], d[mf][j][1]);
            *(float2*)(Ob + (size_t)(m0 + 8) * 256 + n0) = make_float2(d[mf][j][2], d[mf][j][3]);
        }
    }
}

extern "C" void kernel_launch(void* const* d_in, const int* in_sizes, int n_in,
                              void* d_out, int out_size) {
    const float* S = nullptr;
    const float* X = nullptr;
    for (int i = 0; i < n_in; i++) {
        if (in_sizes[i] == 8388608)      S = (const float*)d_in[i];
        else if (in_sizes[i] == 1048576) X = (const float*)d_in[i];
    }
    float* O = (float*)d_out;

    cudaFuncSetAttribute(diffunpool_tf32_v5,
                         cudaFuncAttributeMaxDynamicSharedMemorySize, SM_BYTES);
    dim3 grid(4, 16, 16);
    diffunpool_tf32_v5<<<grid, 128, SM_BYTES>>>(S, X, O);
}

// round 10
// speedup vs baseline: 1.1728x; 1.1728x over previous
#include <cuda_runtime.h>
#include <cstdint>

// DiffUnpool: out[b] = S[b] @ x[b]
//   S: [16, 2048, 256] f32   x: [16, 256, 256] f32   out: [16, 2048, 256] f32
// R10 = R6 (tf32 m16n8k8, CTA 128x128, 4 warps 64x64, cp.async double buffer)
// + fragment register ping-pong: per kk issue raw loads for kk+1, then MMAs
// of kk, then converts for kk+1. Arithmetic identical to R6.

#define A_CHUNK_BYTES 16384          // 128 rows x 128B
#define B_ROWB 544                   // 128 floats + 32B pad
#define B_CHUNK_BYTES (32 * B_ROWB)  // 17408
#define OFF_B (2 * A_CHUNK_BYTES)
#define SM_BYTES (2 * A_CHUNK_BYTES + 2 * B_CHUNK_BYTES)  // 67584

static __device__ __forceinline__ uint32_t cvta_smem(const void* p) {
    uint32_t a;
    asm("{ .reg .u64 t; cvta.to.shared.u64 t, %1; cvt.u32.u64 %0, t; }"
        : "=r"(a) : "l"(p));
    return a;
}
static __device__ __forceinline__ uint32_t tf32cu(uint32_t raw) {
    uint32_t u;
    asm("cvt.rna.tf32.f32 %0, %1;" : "=r"(u) : "f"(__uint_as_float(raw)));
    return u;
}

#define CP16(dst, src) \
    asm volatile("cp.async.cg.shared.global [%0], [%1], 16;" :: "r"(dst), "l"(src))
#define CPCOMMIT() asm volatile("cp.async.commit_group;" ::: "memory")
#define CPWAIT1()  asm volatile("cp.async.wait_group 1;" ::: "memory")

#define LDSM4(r0, r1, r2, r3, a) \
    asm volatile("ldmatrix.sync.aligned.m8n8.x4.shared.b16 {%0,%1,%2,%3}, [%4];" \
                 : "=r"(r0), "=r"(r1), "=r"(r2), "=r"(r3) : "r"(a))
#define LDSS(r, a) \
    asm volatile("ld.shared.b32 %0, [%1];" : "=r"(r) : "r"(a))

#define MMA(d, a, b0, b1) \
    asm volatile("mma.sync.aligned.m16n8k8.row.col.f32.tf32.tf32.f32 " \
                 "{%0,%1,%2,%3},{%4,%5,%6,%7},{%8,%9},{%0,%1,%2,%3};" \
                 : "+f"((d)[0]), "+f"((d)[1]), "+f"((d)[2]), "+f"((d)[3]) \
                 : "r"((a)[0]), "r"((a)[1]), "r"((a)[2]), "r"((a)[3]), "r"(b0), "r"(b1))

extern __shared__ char smbuf[];

__global__ __launch_bounds__(128, 2)
void diffunpool_tf32_v6(const float* __restrict__ S, const float* __restrict__ X,
                        float* __restrict__ O) {
    const int nt = blockIdx.x;   // 0..1
    const int mt = blockIdx.y;   // 0..15
    const int b  = blockIdx.z;   // 0..15

    const float* Sb = S + ((size_t)b * 2048 + (size_t)mt * 128) * 256;
    const float* Xb = X + (size_t)b * 65536 + (size_t)nt * 128;
    float*       Ob = O + ((size_t)b * 2048 + (size_t)mt * 128) * 256 + (size_t)nt * 128;

    const int tid = threadIdx.x, wid = tid >> 5, lane = tid & 31;
    const int wm = (wid & 1) * 64;
    const int wn = (wid >> 1) * 64;
    const uint32_t sb = cvta_smem(smbuf);

    // ---- cp.async staging (R6 verbatim)
    auto issue = [&](int c, int bf) {
        const uint32_t abuf = sb + (uint32_t)bf * A_CHUNK_BYTES;
        const uint32_t bbuf = sb + OFF_B + (uint32_t)bf * B_CHUNK_BYTES;
#pragma unroll
        for (int q = 0; q < 8; q++) {            // A: 128 rows x 8 segs
            int flat = q * 128 + tid;
            int m = flat >> 3, seg = flat & 7;
            const float* src = Sb + (size_t)m * 256 + c * 32 + seg * 4;
            uint32_t dst = abuf + (uint32_t)m * 128 + (uint32_t)((seg ^ (m & 7)) << 4);
            CP16(dst, src);
        }
#pragma unroll
        for (int q = 0; q < 8; q++) {            // B: 32 rows x 32 segs
            int flat = q * 128 + tid;
            int k = flat >> 5, seg = flat & 31;
            const float* src = Xb + (size_t)(c * 32 + k) * 256 + seg * 4;
            uint32_t dst = bbuf + (uint32_t)k * B_ROWB + (uint32_t)(seg << 4);
            CP16(dst, src);
        }
        CPCOMMIT();
    };

    float d[4][8][4];
#pragma unroll
    for (int mf = 0; mf < 4; mf++)
#pragma unroll
        for (int j = 0; j < 8; j++)
#pragma unroll
            for (int r = 0; r < 4; r++) d[mf][j][r] = 0.0f;

    issue(0, 0);
    issue(1, 1);

    // ---- fragment lane addressing (R6 verbatim)
    const int m_low = (lane & 7) + ((lane >> 3) & 1) * 8;
    const int halfk = lane >> 4;
    const int sw    = lane & 7;
    const uint32_t b_lane = (uint32_t)(lane & 3) * B_ROWB
                          + (uint32_t)(wn + (lane >> 2)) * 4;

    for (int c = 0; c < 8; c++) {
        CPWAIT1();
        __syncthreads();

        const uint32_t abuf = sb + (uint32_t)(c & 1) * A_CHUNK_BYTES;
        const uint32_t bbuf = sb + OFF_B + (uint32_t)(c & 1) * B_CHUNK_BYTES + b_lane;
        const uint32_t arow = abuf + (uint32_t)(wm + m_low) * 128;

        uint32_t a[2][4][4];      // ping-pong A fragments
        uint32_t B0[2][8], B1[2][8];

        // ---- preload + convert kk=0
        {
            const uint32_t segsw = (uint32_t)((halfk ^ sw) << 4);
#pragma unroll
            for (int mf = 0; mf < 4; mf++) {
                uint32_t addr = arow + (uint32_t)(mf * 2048) + segsw;
                LDSM4(a[0][mf][0], a[0][mf][1], a[0][mf][2], a[0][mf][3], addr);
            }
#pragma unroll
            for (int j = 0; j < 8; j++) {
                LDSS(B0[0][j], bbuf + j * 32);
                LDSS(B1[0][j], bbuf + j * 32 + 4 * B_ROWB);
            }
#pragma unroll
            for (int mf = 0; mf < 4; mf++)
#pragma unroll
                for (int r = 0; r < 4; r++)
                    a[0][mf][r] = tf32cu(a[0][mf][r]);
#pragma unroll
            for (int j = 0; j < 8; j++) {
                B0[0][j] = tf32cu(B0[0][j]);
                B1[0][j] = tf32cu(B1[0][j]);
            }
        }

#pragma unroll
        for (int kk = 0; kk < 4; kk++) {
            const int cur = kk & 1, nxt = cur ^ 1;

            // (1) raw loads for kk+1 — independent of cur's MMAs
            if (kk < 3) {
                const uint32_t segsw = (uint32_t)(((2 * (kk + 1) + halfk) ^ sw) << 4);
#pragma unroll
                for (int mf = 0; mf < 4; mf++) {
                    uint32_t addr = arow + (uint32_t)(mf * 2048) + segsw;
                    LDSM4(a[nxt][mf][0], a[nxt][mf][1], a[nxt][mf][2], a[nxt][mf][3], addr);
                }
                const uint32_t bk = bbuf + (uint32_t)((kk + 1) * 8 * B_ROWB);
#pragma unroll
                for (int j = 0; j < 8; j++) {
                    LDSS(B0[nxt][j], bk + j * 32);
                    LDSS(B1[nxt][j], bk + j * 32 + 4 * B_ROWB);
                }
            }

            // (2) 32 MMAs of kk (operands converted previously)
#pragma unroll
            for (int mf = 0; mf < 4; mf++)
#pragma unroll
                for (int j = 0; j < 8; j++)
                    MMA(d[mf][j], a[cur][mf], B0[cur][j], B1[cur][j]);

            // (3) convert kk+1's fragments (off the MMA critical path)
            if (kk < 3) {
#pragma unroll
                for (int mf = 0; mf < 4; mf++)
#pragma unroll
                    for (int r = 0; r < 4; r++)
                        a[nxt][mf][r] = tf32cu(a[nxt][mf][r]);
#pragma unroll
                for (int j = 0; j < 8; j++) {
                    B0[nxt][j] = tf32cu(B0[nxt][j]);
                    B1[nxt][j] = tf32cu(B1[nxt][j]);
                }
            }
        }
        __syncthreads();
        if (c < 6) issue(c + 2, c & 1);
    }

    // ---- epilogue (R6 verbatim)
    const int group = lane >> 2;
    const int tcol  = (lane & 3) * 2;
#pragma unroll
    for (int mf = 0; mf < 4; mf++) {
        int m0 = wm + mf * 16 + group;
#pragma unroll
        for (int j = 0; j < 8; j++) {
            int n0 = wn + j * 8 + tcol;
            *(float2*)(Ob + (size_t)m0 * 256 + n0)       = make_float2(d[mf][j][0], d[mf][j][1]);
            *(float2*)(Ob + (size_t)(m0 + 8) * 256 + n0) = make_float2(d[mf][j][2], d[mf][j][3]);
        }
    }
}

extern "C" void kernel_launch(void* const* d_in, const int* in_sizes, int n_in,
                              void* d_out, int out_size) {
    const float* S = nullptr;
    const float* X = nullptr;
    for (int i = 0; i < n_in; i++) {
        if (in_sizes[i] == 8388608)      S = (const float*)d_in[i];
        else if (in_sizes[i] == 1048576) X = (const float*)d_in[i];
    }
    float* O = (float*)d_out;

    cudaFuncSetAttribute(diffunpool_tf32_v6,
                         cudaFuncAttributeMaxDynamicSharedMemorySize, SM_BYTES);
    dim3 grid(2, 16, 16);
    diffunpool_tf32_v6<<<grid, 128, SM_BYTES>>>(S, X, O);
}

// round 11
// speedup vs baseline: 1.5384x; 1.3117x over previous
#include <cuda_runtime.h>
#include <cuda_fp16.h>
#include <cstdint>

// DiffUnpool: out[b] = S[b] @ x[b]
//   S: [16, 2048, 256] f32   x: [16, 256, 256] f32   out: [16, 2048, 256] f32
// Single-product fp16 m16n8k16 (same 10-bit mantissa as the tf32 path that
// measured 2.8e-4, but 2x MACs per tensor-pipe slot). fp32 accumulate.
// CTA 128x128, 4 warps 64x64, K-chunks of 32, register-staged fp32->fp16,
// double-buffered smem, one __syncthreads per chunk (R5-proven protocol).

#define A_BUF 8192                    // 128 rows x 64B (32 fp16)
#define B_BUF 8192                    // 32 rows x 256B (128 fp16)
#define OFF_B (2 * A_BUF)             // 16384
#define SM_BYTES (2 * A_BUF + 2 * B_BUF)   // 32768

static __device__ __forceinline__ uint32_t cvta_smem(const void* p) {
    uint32_t a;
    asm("{ .reg .u64 t; cvta.to.shared.u64 t, %1; cvt.u32.u64 %0, t; }"
        : "=r"(a) : "l"(p));
    return a;
}
static __device__ __forceinline__ uint32_t h2(float x, float y) {
    __half2 h = __floats2half2_rn(x, y);
    return *(uint32_t*)&h;
}
static __device__ __forceinline__ uint4 cvt8(float4 a, float4 b) {
    return make_uint4(h2(a.x, a.y), h2(a.z, a.w), h2(b.x, b.y), h2(b.z, b.w));
}

#define LDSM4(r0, r1, r2, r3, a) \
    asm volatile("ldmatrix.sync.aligned.m8n8.x4.shared.b16 {%0,%1,%2,%3}, [%4];" \
                 : "=r"(r0), "=r"(r1), "=r"(r2), "=r"(r3) : "r"(a))
#define LDSM4T(r0, r1, r2, r3, a) \
    asm volatile("ldmatrix.sync.aligned.m8n8.x4.trans.shared.b16 {%0,%1,%2,%3}, [%4];" \
                 : "=r"(r0), "=r"(r1), "=r"(r2), "=r"(r3) : "r"(a))
#define MMAF16(d, a, b0, b1) \
    asm volatile("mma.sync.aligned.m16n8k16.row.col.f32.f16.f16.f32 " \
                 "{%0,%1,%2,%3},{%4,%5,%6,%7},{%8,%9},{%0,%1,%2,%3};" \
                 : "+f"((d)[0]), "+f"((d)[1]), "+f"((d)[2]), "+f"((d)[3]) \
                 : "r"((a)[0]), "r"((a)[1]), "r"((a)[2]), "r"((a)[3]), "r"(b0), "r"(b1))

extern __shared__ char smbuf[];

__global__ __launch_bounds__(128, 2)
void diffunpool_f16(const float* __restrict__ S, const float* __restrict__ X,
                    float* __restrict__ O) {
    const int nt = blockIdx.x;   // 0..1
    const int mt = blockIdx.y;   // 0..15
    const int b  = blockIdx.z;   // 0..15

    const float* Sb = S + ((size_t)b * 2048 + (size_t)mt * 128) * 256;
    const float* Xb = X + (size_t)b * 65536 + (size_t)nt * 128;
    float*       Ob = O + ((size_t)b * 2048 + (size_t)mt * 128) * 256 + (size_t)nt * 128;

    const int tid = threadIdx.x, wid = tid >> 5, lane = tid & 31;
    const int wm = (wid & 1) * 64;
    const int wn = (wid >> 1) * 64;
    const uint32_t sb = cvta_smem(smbuf);

    // ---- staging mappings (per q of 4, offsets += q*2048 bytes / strides below)
    // A: thread owns seg (tid&3, 16B fp16 <- 32B fp32) of row m = q*32 + (tid>>2)
    const int a_m = tid >> 2, a_seg = tid & 3;
    const float*   pA   = Sb + (size_t)a_m * 256 + a_seg * 8;
    const uint32_t aSts = (uint32_t)a_m * 64 + (uint32_t)((a_seg ^ ((a_m >> 1) & 3)) << 4);
    // B: thread owns seg (tid&15) of k-row k = q*8 + (tid>>4)
    const int b_k = tid >> 4, b_seg = tid & 15;
    const float*   pB   = Xb + (size_t)b_k * 256 + b_seg * 8;
    const uint32_t bSts = OFF_B + (uint32_t)b_k * 256 + (uint32_t)((b_seg ^ (b_k & 7)) << 4);

    // ---- fragment addressing
    const int m_low = (lane & 7) + 8 * ((lane >> 3) & 1);
    const int halfk = lane >> 4;
    uint32_t rowA[4], swzA[4];
#pragma unroll
    for (int mf = 0; mf < 4; mf++) {
        int row = wm + mf * 16 + m_low;
        rowA[mf] = (uint32_t)row * 64;
        swzA[mf] = (uint32_t)((row >> 1) & 3);
    }
    const int b_kl  = lane & 15;
    const int kswz  = b_kl & 7;
    const int b_c0  = (wn >> 3) + (lane >> 4);     // n8-block index base
    const uint32_t bRow = (uint32_t)b_kl * 256;

    float d[4][8][4];
#pragma unroll
    for (int mf = 0; mf < 4; mf++)
#pragma unroll
        for (int j = 0; j < 8; j++)
#pragma unroll
            for (int r = 0; r < 4; r++) d[mf][j][r] = 0.0f;

    // ---- prologue: LDG chunk 0
    float4 va[8], vb[8];
#pragma unroll
    for (int q = 0; q < 4; q++) {
        va[2*q]   = *(const float4*)(pA + (size_t)q * 8192);
        va[2*q+1] = *(const float4*)(pA + (size_t)q * 8192 + 4);
        vb[2*q]   = *(const float4*)(pB + (size_t)q * 2048);
        vb[2*q+1] = *(const float4*)(pB + (size_t)q * 2048 + 4);
    }

    for (int c = 0; c < 8; c++) {
        const uint32_t aOff = (uint32_t)(c & 1) * A_BUF;
        const uint32_t bOff = (uint32_t)(c & 1) * B_BUF;

        // ---- convert + store chunk c
#pragma unroll
        for (int q = 0; q < 4; q++) {
            *(uint4*)(smbuf + aOff + aSts + q * 2048) = cvt8(va[2*q], va[2*q+1]);
            *(uint4*)(smbuf + bOff + bSts + q * 2048) = cvt8(vb[2*q], vb[2*q+1]);
        }
        __syncthreads();

        // ---- prefetch chunk c+1 (regs live across compute; hidden under MMAs)
        if (c < 7) {
            const float* nA = pA + (c + 1) * 32;
            const float* nB = pB + (size_t)(c + 1) * 32 * 256;
#pragma unroll
            for (int q = 0; q < 4; q++) {
                va[2*q]   = *(const float4*)(nA + (size_t)q * 8192);
                va[2*q+1] = *(const float4*)(nA + (size_t)q * 8192 + 4);
                vb[2*q]   = *(const float4*)(nB + (size_t)q * 2048);
                vb[2*q+1] = *(const float4*)(nB + (size_t)q * 2048 + 4);
            }
        }

        // ---- compute chunk c: 2 k16 steps
#pragma unroll
        for (int ks = 0; ks < 2; ks++) {
            uint32_t a[4][4];
#pragma unroll
            for (int mf = 0; mf < 4; mf++) {
                uint32_t seg  = (uint32_t)(2 * ks + halfk);
                uint32_t addr = sb + aOff + rowA[mf] + ((seg ^ swzA[mf]) << 4);
                LDSM4(a[mf][0], a[mf][1], a[mf][2], a[mf][3], addr);
            }
            uint32_t bb[4][4];
            const uint32_t bkoff = sb + OFF_B + bOff + (uint32_t)(ks * 4096) + bRow;
#pragma unroll
            for (int nb = 0; nb < 4; nb++) {
                uint32_t chunk = (uint32_t)((b_c0 + nb * 2) ^ kswz);
                LDSM4T(bb[nb][0], bb[nb][1], bb[nb][2], bb[nb][3], bkoff + (chunk << 4));
            }
#pragma unroll
            for (int mf = 0; mf < 4; mf++)
#pragma unroll
                for (int nb = 0; nb < 4; nb++) {
                    MMAF16(d[mf][2*nb],   a[mf], bb[nb][0], bb[nb][1]);
                    MMAF16(d[mf][2*nb+1], a[mf], bb[nb][2], bb[nb][3]);
                }
        }
        // single barrier/chunk: STS(c+1) hits the other buffer; barrier above
        // ordered compute(c-1) (that buffer's readers) before it in all warps.
    }

    // ---- epilogue
    const int group = lane >> 2;
    const int tcol  = (lane & 3) * 2;
#pragma unroll
    for (int mf = 0; mf < 4; mf++) {
        int m0 = wm + mf * 16 + group;
#pragma unroll
        for (int j = 0; j < 8; j++) {
            int n0 = wn + j * 8 + tcol;
            *(float2*)(Ob + (size_t)m0 * 256 + n0)       = make_float2(d[mf][j][0], d[mf][j][1]);
            *(float2*)(Ob + (size_t)(m0 + 8) * 256 + n0) = make_float2(d[mf][j][2], d[mf][j][3]);
        }
    }
}

extern "C" void kernel_launch(void* const* d_in, const int* in_sizes, int n_in,
                              void* d_out, int out_size) {
    const float* S = nullptr;
    const float* X = nullptr;
    for (int i = 0; i < n_in; i++) {
        if (in_sizes[i] == 8388608)      S = (const float*)d_in[i];
        else if (in_sizes[i] == 1048576) X = (const float*)d_in[i];
    }
    float* O = (float*)d_out;

    cudaFuncSetAttribute(diffunpool_f16,
                         cudaFuncAttributeMaxDynamicSharedMemorySize, SM_BYTES);
    dim3 grid(2, 16, 16);
    diffunpool_f16<<<grid, 128, SM_BYTES>>>(S, X, O);
}

// round 12
// speedup vs baseline: 1.6620x; 1.0804x over previous
#include <cuda_runtime.h>
#include <cuda_fp16.h>
#include <cstdint>

// DiffUnpool: out[b] = S[b] @ x[b]
//   S: [16, 2048, 256] f32   x: [16, 256, 256] f32   out: [16, 2048, 256] f32
// R12 = R11 (fp16 m16n8k16, CTA 128x128, 4 warps 64x64) with x pre-converted
// to fp16 once (tiny pre-pass kernel into __device__ scratch); B then streams
// via cp.async fp16 (no per-CTA fp32 load + convert). A staging unchanged.

#define A_BUF 8192                    // 128 rows x 64B fp16
#define B_BUF 8192                    // 32 rows x 256B fp16
#define OFF_B (2 * A_BUF)             // 16384
#define SM_BYTES (2 * A_BUF + 2 * B_BUF)   // 32768

__device__ __align__(16) __half g_X16[16 * 256 * 256];   // 2 MB scratch

// ---- pre-pass: x fp32 -> fp16 (one uint4 = 8 halves per thread)
__global__ void convert_x(const float* __restrict__ X) {
    int i = blockIdx.x * blockDim.x + threadIdx.x;        // 0..131071
    const float4* src = (const float4*)X;
    float4 v0 = src[2 * i], v1 = src[2 * i + 1];
    __half2 h0 = __floats2half2_rn(v0.x, v0.y);
    __half2 h1 = __floats2half2_rn(v0.z, v0.w);
    __half2 h2 = __floats2half2_rn(v1.x, v1.y);
    __half2 h3 = __floats2half2_rn(v1.z, v1.w);
    uint4 u = make_uint4(*(uint32_t*)&h0, *(uint32_t*)&h1,
                         *(uint32_t*)&h2, *(uint32_t*)&h3);
    ((uint4*)g_X16)[i] = u;
}

static __device__ __forceinline__ uint32_t cvta_smem(const void* p) {
    uint32_t a;
    asm("{ .reg .u64 t; cvta.to.shared.u64 t, %1; cvt.u32.u64 %0, t; }"
        : "=r"(a) : "l"(p));
    return a;
}
static __device__ __forceinline__ uint32_t h2u(float x, float y) {
    __half2 h = __floats2half2_rn(x, y);
    return *(uint32_t*)&h;
}
static __device__ __forceinline__ uint4 cvt8(float4 a, float4 b) {
    return make_uint4(h2u(a.x, a.y), h2u(a.z, a.w), h2u(b.x, b.y), h2u(b.z, b.w));
}

#define CP16(dst, src) \
    asm volatile("cp.async.cg.shared.global [%0], [%1], 16;" :: "r"(dst), "l"(src))
#define CPCOMMIT() asm volatile("cp.async.commit_group;" ::: "memory")
#define CPWAIT1()  asm volatile("cp.async.wait_group 1;" ::: "memory")

#define LDSM4(r0, r1, r2, r3, a) \
    asm volatile("ldmatrix.sync.aligned.m8n8.x4.shared.b16 {%0,%1,%2,%3}, [%4];" \
                 : "=r"(r0), "=r"(r1), "=r"(r2), "=r"(r3) : "r"(a))
#define LDSM4T(r0, r1, r2, r3, a) \
    asm volatile("ldmatrix.sync.aligned.m8n8.x4.trans.shared.b16 {%0,%1,%2,%3}, [%4];" \
                 : "=r"(r0), "=r"(r1), "=r"(r2), "=r"(r3) : "r"(a))
#define MMAF16(d, a, b0, b1) \
    asm volatile("mma.sync.aligned.m16n8k16.row.col.f32.f16.f16.f32 " \
                 "{%0,%1,%2,%3},{%4,%5,%6,%7},{%8,%9},{%0,%1,%2,%3};" \
                 : "+f"((d)[0]), "+f"((d)[1]), "+f"((d)[2]), "+f"((d)[3]) \
                 : "r"((a)[0]), "r"((a)[1]), "r"((a)[2]), "r"((a)[3]), "r"(b0), "r"(b1))

__global__ __launch_bounds__(128, 2)
void diffunpool_f16_v2(const float* __restrict__ S, float* __restrict__ O) {
    __shared__ __align__(16) char smbuf[SM_BYTES];

    const int nt = blockIdx.x;   // 0..1
    const int mt = blockIdx.y;   // 0..15
    const int b  = blockIdx.z;   // 0..15

    const float*  Sb  = S + ((size_t)b * 2048 + (size_t)mt * 128) * 256;
    const __half* Xb  = g_X16 + (size_t)b * 65536 + (size_t)nt * 128;
    float*        Ob  = O + ((size_t)b * 2048 + (size_t)mt * 128) * 256 + (size_t)nt * 128;

    const int tid = threadIdx.x, wid = tid >> 5, lane = tid & 31;
    const int wm = (wid & 1) * 64;
    const int wn = (wid >> 1) * 64;
    const uint32_t sb = cvta_smem(smbuf);

    // ---- A staging (R11 verbatim): thread owns seg (tid&3) of rows tid>>2 + 32q
    const int a_m = tid >> 2, a_seg = tid & 3;
    const float*   pA   = Sb + (size_t)a_m * 256 + a_seg * 8;
    const uint32_t aSts = (uint32_t)a_m * 64 + (uint32_t)((a_seg ^ ((a_m >> 1) & 3)) << 4);

    // ---- B cp.async mapping: 32 rows x 16 segs = 512 pieces, 4/thread
    //      smem layout/swizzle identical to R11's B (seg ^ (k&7))
    auto issueB = [&](int c, int bf) {
        const uint32_t bbuf = sb + OFF_B + (uint32_t)bf * B_BUF;
#pragma unroll
        for (int q = 0; q < 4; q++) {
            int flat = q * 128 + tid;
            int k = flat >> 4, s = flat & 15;
            const __half* src = Xb + (size_t)(c * 32 + k) * 256 + s * 8;
            uint32_t dst = bbuf + (uint32_t)k * 256 + (uint32_t)((s ^ (k & 7)) << 4);
            CP16(dst, src);
        }
        CPCOMMIT();
    };

    // ---- fragment addressing (R11 verbatim)
    const int m_low = (lane & 7) + 8 * ((lane >> 3) & 1);
    const int halfk = lane >> 4;
    uint32_t rowA[4], swzA[4];
#pragma unroll
    for (int mf = 0; mf < 4; mf++) {
        int row = wm + mf * 16 + m_low;
        rowA[mf] = (uint32_t)row * 64;
        swzA[mf] = (uint32_t)((row >> 1) & 3);
    }
    const int b_kl  = lane & 15;
    const int kswz  = b_kl & 7;
    const int b_c0  = (wn >> 3) + (lane >> 4);
    const uint32_t bRow = (uint32_t)b_kl * 256;

    float d[4][8][4];
#pragma unroll
    for (int mf = 0; mf < 4; mf++)
#pragma unroll
        for (int j = 0; j < 8; j++)
#pragma unroll
            for (int r = 0; r < 4; r++) d[mf][j][r] = 0.0f;

    // ---- prologue: A chunk 0 in regs; B chunks 0,1 via cp.async
    float4 va[8];
#pragma unroll
    for (int q = 0; q < 4; q++) {
        va[2*q]   = *(const float4*)(pA + (size_t)q * 8192);
        va[2*q+1] = *(const float4*)(pA + (size_t)q * 8192 + 4);
    }
    issueB(0, 0);
    issueB(1, 1);

    for (int c = 0; c < 8; c++) {
        const uint32_t aOff = (uint32_t)(c & 1) * A_BUF;
        const uint32_t bOff = (uint32_t)(c & 1) * B_BUF;

        // ---- convert + store A chunk c
#pragma unroll
        for (int q = 0; q < 4; q++)
            *(uint4*)(smbuf + aOff + aSts + q * 2048) = cvt8(va[2*q], va[2*q+1]);

        CPWAIT1();                 // B chunk c resident
        __syncthreads();           // A(c) visible; B(c) visible

        // ---- prefetch A chunk c+1 (hidden under compute)
        if (c < 7) {
            const float* nA = pA + (c + 1) * 32;
#pragma unroll
            for (int q = 0; q < 4; q++) {
                va[2*q]   = *(const float4*)(nA + (size_t)q * 8192);
                va[2*q+1] = *(const float4*)(nA + (size_t)q * 8192 + 4);
            }
        }

        // ---- compute chunk c: 2 k16 steps (R11 verbatim)
#pragma unroll
        for (int ks = 0; ks < 2; ks++) {
            uint32_t a[4][4];
#pragma unroll
            for (int mf = 0; mf < 4; mf++) {
                uint32_t seg  = (uint32_t)(2 * ks + halfk);
                uint32_t addr = sb + aOff + rowA[mf] + ((seg ^ swzA[mf]) << 4);
                LDSM4(a[mf][0], a[mf][1], a[mf][2], a[mf][3], addr);
            }
            uint32_t bb[4][4];
            const uint32_t bkoff = sb + OFF_B + bOff + (uint32_t)(ks * 4096) + bRow;
#pragma unroll
            for (int nb = 0; nb < 4; nb++) {
                uint32_t chunk = (uint32_t)((b_c0 + nb * 2) ^ kswz);
                LDSM4T(bb[nb][0], bb[nb][1], bb[nb][2], bb[nb][3], bkoff + (chunk << 4));
            }
#pragma unroll
            for (int mf = 0; mf < 4; mf++)
#pragma unroll
                for (int nb = 0; nb < 4; nb++) {
                    MMAF16(d[mf][2*nb],   a[mf], bb[nb][0], bb[nb][1]);
                    MMAF16(d[mf][2*nb+1], a[mf], bb[nb][2], bb[nb][3]);
                }
        }
        __syncthreads();           // all warps done reading Bbuf[c&1]
        if (c < 6) issueB(c + 2, c & 1);
    }

    // ---- epilogue (R11 verbatim)
    const int group = lane >> 2;
    const int tcol  = (lane & 3) * 2;
#pragma unroll
    for (int mf = 0; mf < 4; mf++) {
        int m0 = wm + mf * 16 + group;
#pragma unroll
        for (int j = 0; j < 8; j++) {
            int n0 = wn + j * 8 + tcol;
            *(float2*)(Ob + (size_t)m0 * 256 + n0)       = make_float2(d[mf][j][0], d[mf][j][1]);
            *(float2*)(Ob + (size_t)(m0 + 8) * 256 + n0) = make_float2(d[mf][j][2], d[mf][j][3]);
        }
    }
}

extern "C" void kernel_launch(void* const* d_in, const int* in_sizes, int n_in,
                              void* d_out, int out_size) {
    const float* S = nullptr;
    const float* X = nullptr;
    for (int i = 0; i < n_in; i++) {
        if (in_sizes[i] == 8388608)      S = (const float*)d_in[i];
        else if (in_sizes[i] == 1048576) X = (const float*)d_in[i];
    }
    float* O = (float*)d_out;

    convert_x<<<512, 256>>>(X);                 // 131072 threads, 8 floats each
    dim3 grid(2, 16, 16);
    diffunpool_f16_v2<<<grid, 128>>>(S, O);
}